// round 7
// baseline (speedup 1.0000x reference)
#include <cuda_runtime.h>
#include <cuda_bf16.h>
#include <math.h>
#include <stdint.h>

// VanillaLSTM persistent kernel (sm_103 HMMA bf16-split), warp-autonomous,
// progressive per-chunk dataflow sync + depth-3 cp.async pipeline.
// 96 CTAs x 256 threads. Weights SMEM-resident. Warp w touches only h rows
// [16w,16w+16); per-(group,warp) counters; warp gates issue(c) on counter c only.

#define ROWS 128
#define HDIM 768
#define SEQ  256
#define NCTA 96
#define NCHUNK 12
#define APITCH 144

// smem layout (bytes)
#define WS_HI 0
#define WS_LO 55296              // 12 chunks * 32 rows * 144
#define A_BASE 110592            // 8 warps * 3 bufs * 4608 (hi 2304 + lo 2304)
#define SMEM_TOTAL (A_BASE + 8 * 3 * 4608)   // 221184

__device__ __align__(16) __nv_bfloat16 g_hhi[2][ROWS * HDIM];
__device__ __align__(16) __nv_bfloat16 g_hlo[2][ROWS * HDIM];
__device__ __align__(16) float         g_c[ROWS * HDIM];
__device__ __align__(16) __nv_bfloat16 g_Bhi[NCTA * NCHUNK * 2048];
__device__ __align__(16) __nv_bfloat16 g_Blo[NCTA * NCHUNK * 2048];
__device__ __align__(16) float2        g_wxb[NCTA * 32];
__device__ __align__(128) unsigned     g_ctr[NCHUNK * 8][32];  // (group, warp), 128B apart

// ---------------------------------------------------------------------------
__device__ __forceinline__ uint32_t smem_u32(const void* p) {
    uint32_t a;
    asm("{ .reg .u64 t; cvta.to.shared.u64 t, %1; cvt.u32.u64 %0, t; }" : "=r"(a) : "l"(p));
    return a;
}
__device__ __forceinline__ void cpa16(uint32_t dst, const void* src) {
    asm volatile("cp.async.cg.shared.global [%0], [%1], 16;" :: "r"(dst), "l"(src) : "memory");
}
__device__ __forceinline__ void cp_commit() {
    asm volatile("cp.async.commit_group;" ::: "memory");
}
__device__ __forceinline__ void cp_wait2() {
    asm volatile("cp.async.wait_group 2;" ::: "memory");
}
__device__ __forceinline__ void cp_wait1() {
    asm volatile("cp.async.wait_group 1;" ::: "memory");
}
__device__ __forceinline__ void cp_wait0() {
    asm volatile("cp.async.wait_group 0;" ::: "memory");
}
__device__ __forceinline__ void ldsm4(uint32_t* r, uint32_t addr) {
    asm volatile("ldmatrix.sync.aligned.m8n8.x4.shared.b16 {%0,%1,%2,%3}, [%4];"
                 : "=r"(r[0]), "=r"(r[1]), "=r"(r[2]), "=r"(r[3]) : "r"(addr));
}
__device__ __forceinline__ void mma_bf16(float* d, const uint32_t* a, uint32_t b0, uint32_t b1) {
    asm volatile(
        "mma.sync.aligned.m16n8k16.row.col.f32.bf16.bf16.f32 "
        "{%0,%1,%2,%3}, {%4,%5,%6,%7}, {%8,%9}, {%0,%1,%2,%3};"
        : "+f"(d[0]), "+f"(d[1]), "+f"(d[2]), "+f"(d[3])
        : "r"(a[0]), "r"(a[1]), "r"(a[2]), "r"(a[3]), "r"(b0), "r"(b1));
}

// ---------------------------------------------------------------------------
__global__ void init_state(const float* __restrict__ h0, const float* __restrict__ c0) {
    int i = blockIdx.x * 256 + threadIdx.x;
    if (i < NCHUNK * 8) g_ctr[i][0] = 0u;
    if (i < ROWS * HDIM) {
        float v = h0[i];
        __nv_bfloat16 hi = __float2bfloat16(v);
        g_hhi[0][i] = hi;
        g_hlo[0][i] = __float2bfloat16(v - __bfloat162float(hi));
        g_c[i] = c0[i];
    }
}

// ---------------------------------------------------------------------------
__global__ void repack(const float* __restrict__ Wi, const float* __restrict__ Wf,
                       const float* __restrict__ Wc, const float* __restrict__ Wo,
                       const float* __restrict__ bi, const float* __restrict__ bf,
                       const float* __restrict__ bc, const float* __restrict__ bo) {
    int idx = blockIdx.x * 256 + threadIdx.x;
    const int TOT = NCTA * NCHUNK * 2048;
    if (idx < TOT) {
        int kl  = idx & 63;
        int n   = (idx >> 6) & 31;
        int blk = idx >> 11;
        int kc  = blk % NCHUNK;
        int nb  = blk / NCHUNK;
        int gate = n & 3;
        int j = nb * 8 + (n >> 2);
        const float* W = (gate == 0) ? Wi : (gate == 1) ? Wf : (gate == 2) ? Wc : Wo;
        float v = W[(1 + kc * 64 + kl) * HDIM + j];
        __nv_bfloat16 hi = __float2bfloat16(v);
        g_Bhi[idx] = hi;
        g_Blo[idx] = __float2bfloat16(v - __bfloat162float(hi));
    }
    if (idx < NCTA * 32) {
        int n = idx & 31;
        int nb = idx >> 5;
        int gate = n & 3;
        int j = nb * 8 + (n >> 2);
        const float* W = (gate == 0) ? Wi : (gate == 1) ? Wf : (gate == 2) ? Wc : Wo;
        const float* B = (gate == 0) ? bi : (gate == 1) ? bf : (gate == 2) ? bc : bo;
        g_wxb[idx] = make_float2(W[j], B[j]);
    }
}

// ---------------------------------------------------------------------------
__global__ void __launch_bounds__(256, 1) lstm_persistent(const float* __restrict__ x) {
    extern __shared__ char smem[];
    const uint32_t sb = smem_u32(smem);
    const int tid = threadIdx.x;
    const int lane = tid & 31, wid = tid >> 5;
    const int nb = blockIdx.x;

    // ---------------- prologue: stage W into smem (once) ----------------
    {
        const uint4* __restrict__ sh = ((const uint4*)g_Bhi) + nb * (NCHUNK * 256);
        const uint4* __restrict__ sl = ((const uint4*)g_Blo) + nb * (NCHUNK * 256);
        for (int i = tid; i < NCHUNK * 256; i += 256) {
            int c = i >> 8, r = i & 255;
            int n = r >> 3, k8 = r & 7;
            uint32_t off = (uint32_t)(c * 4608 + n * APITCH + k8 * 16);
            *(uint4*)(smem + WS_HI + off) = sh[i];
            *(uint4*)(smem + WS_LO + off) = sl[i];
        }
    }
    __syncthreads();

    const int w16 = wid * 16;
    const uint32_t abase = sb + A_BASE + wid * (3 * 4608);

    // ldmatrix lane offsets
    const int sel = lane >> 3, li = lane & 7;
    const uint32_t aoff = (uint32_t)((li + (sel & 1) * 8) * APITCH + (sel >> 1) * 16);
    const uint32_t boff = (uint32_t)((li + (sel >> 1) * 8) * APITCH + (sel & 1) * 16);

    // epilogue constants
    const int my_row = w16 + (lane >> 2) + (lane & 1) * 8;
    const float* __restrict__ xrow = x + (my_row >> 1) * 512 + (my_row & 1);

    // registers: wxb, cell state
    float2 wxi[4], wxf[4], wxc[4], wxo[4];
    float  creg[4];
    {
        const float2* __restrict__ wxbp = g_wxb + nb * 32;
#pragma unroll
        for (int nt = 0; nt < 4; ++nt) {
            int jl = nt * 2 + ((lane & 3) >> 1);
            wxi[nt] = wxbp[4 * jl + 0];
            wxf[nt] = wxbp[4 * jl + 1];
            wxc[nt] = wxbp[4 * jl + 2];
            wxo[nt] = wxbp[4 * jl + 3];
            creg[nt] = g_c[my_row * HDIM + nb * 8 + jl];
        }
    }

    // sync pointers: lane j (<12) polls counter of chunk-group j for this warp id
    const unsigned* __restrict__ pollp =
        (lane < NCHUNK) ? &g_ctr[lane * 8 + wid][0] : &g_ctr[0][0];
    unsigned* __restrict__ relp = &g_ctr[(nb >> 3) * 8 + wid][0];

    for (int t = 0; t < SEQ; ++t) {
        const int par = t & 1;
        const __nv_bfloat16* __restrict__ hhi = g_hhi[par];
        const __nv_bfloat16* __restrict__ hlo = g_hlo[par];
        __nv_bfloat16* __restrict__ ohi = g_hhi[par ^ 1];
        __nv_bfloat16* __restrict__ olo = g_hlo[par ^ 1];
        const unsigned tgt = 8u * (unsigned)t;

        // progressive dataflow wait: only need chunk c's producers before issue(c)
        auto wait_chunk = [&](int c) {
            if (t == 0) return;
            for (;;) {
                unsigned v = 0;
                if (lane < NCHUNK) {
                    asm volatile("ld.acquire.gpu.global.u32 %0, [%1];"
                                 : "=r"(v) : "l"(pollp) : "memory");
                }
                unsigned m = __ballot_sync(0xffffffffu, v >= tgt);
                if ((m >> c) & 1u) break;
            }
        };

        // per-warp A staging: 16 rows x 64 k, hi+lo, buffer c%3
        auto issue = [&](int c) {
            const uint32_t bufs = abase + (uint32_t)(c % 3) * 4608;
#pragma unroll
            for (int i = 0; i < 4; ++i) {
                int o = lane * 4 + i;            // 0..127
                int row = o >> 3, seg = o & 7;
                uint32_t dst = bufs + (uint32_t)(row * APITCH + seg * 16);
                const int so = (w16 + row) * HDIM + c * 64 + seg * 8;
                cpa16(dst, hhi + so);
                cpa16(dst + 2304, hlo + so);
            }
            cp_commit();
        };

        float d[4][4];
#pragma unroll
        for (int i = 0; i < 4; i++)
#pragma unroll
            for (int k = 0; k < 4; k++) d[i][k] = 0.f;

        wait_chunk(0); issue(0);
        wait_chunk(1); issue(1);
        wait_chunk(2); issue(2);

#pragma unroll 3
        for (int c = 0; c < NCHUNK; ++c) {
            if (c <= NCHUNK - 3)      cp_wait2();
            else if (c == NCHUNK - 2) cp_wait1();
            else                      cp_wait0();
            __syncwarp();
            const uint32_t abuf = abase + (uint32_t)(c % 3) * 4608;
            const uint32_t wbase = sb + (uint32_t)(c * 4608);
#pragma unroll
            for (int ks = 0; ks < 4; ++ks) {
                uint32_t ah[4], al[4];
                ldsm4(ah, abuf + aoff + ks * 32);
                ldsm4(al, abuf + 2304 + aoff + ks * 32);
#pragma unroll
                for (int p = 0; p < 2; ++p) {
                    uint32_t bh[4], bl[4];
                    const uint32_t bb = wbase + boff + ks * 32 + p * (16 * APITCH);
                    ldsm4(bh, bb + WS_HI);
                    ldsm4(bl, bb + WS_LO);
                    mma_bf16(d[2 * p],     ah, bh[0], bh[1]);
                    mma_bf16(d[2 * p],     ah, bl[0], bl[1]);
                    mma_bf16(d[2 * p],     al, bh[0], bh[1]);
                    mma_bf16(d[2 * p + 1], ah, bh[2], bh[3]);
                    mma_bf16(d[2 * p + 1], ah, bl[2], bl[3]);
                    mma_bf16(d[2 * p + 1], al, bh[2], bh[3]);
                }
            }
            __syncwarp();
            if (c + 3 < NCHUNK) { wait_chunk(c + 3); issue(c + 3); }
        }

        // ---------------- fused LSTM epilogue (warp-local rows) ----------------
        const float xv = xrow[2 * t];
#pragma unroll
        for (int nt = 0; nt < 4; ++nt) {
            const int jl = nt * 2 + ((lane & 3) >> 1);
            float p0 = __shfl_xor_sync(0xffffffffu, d[nt][0], 1);
            float p1 = __shfl_xor_sync(0xffffffffu, d[nt][1], 1);
            float p2 = __shfl_xor_sync(0xffffffffu, d[nt][2], 1);
            float p3 = __shfl_xor_sync(0xffffffffu, d[nt][3], 1);
            float gi, gf, gc, go;
            if (!(lane & 1)) { gi = d[nt][0]; gf = d[nt][1]; gc = p0; go = p1; }
            else             { gi = p2;       gf = p3;       gc = d[nt][2]; go = d[nt][3]; }
            float pi = gi + xv * wxi[nt].x + wxi[nt].y;
            float pf = gf + xv * wxf[nt].x + wxf[nt].y;
            float pc = gc + xv * wxc[nt].x + wxc[nt].y;
            float po = go + xv * wxo[nt].x + wxo[nt].y;
            float ig = __fdividef(1.f, 1.f + __expf(-pi));
            float fg = __fdividef(1.f, 1.f + __expf(-pf));
            float thc = 1.f - __fdividef(2.f, 1.f + __expf(2.f * pc));
            float cn = fg * creg[nt] + ig * thc;
            float thn = 1.f - __fdividef(2.f, 1.f + __expf(2.f * cn));
            float hn = po * thn;            // no sigmoid on output gate
            creg[nt] = cn;
            const int idx = my_row * HDIM + nb * 8 + jl;
            __nv_bfloat16 hi = __float2bfloat16(hn);
            ohi[idx] = hi;
            olo[idx] = __float2bfloat16(hn - __bfloat162float(hi));
        }

        // publish this warp's rows (release orders prior stores)
        if (t + 1 < SEQ) {
            __syncwarp();
            if (lane == 0) {
                asm volatile("red.release.gpu.global.add.u32 [%0], %1;"
                             :: "l"(relp), "r"(1u) : "memory");
            }
        }
    }
}

// ---------------------------------------------------------------------------
__global__ void out_final(const float* __restrict__ Wout,
                          const float* __restrict__ bout,
                          float* __restrict__ out) {
    int gtid = blockIdx.x * 128 + threadIdx.x;
    int r = gtid >> 5, lane = gtid & 31;
    float s = 0.f;
    for (int k = lane; k < HDIM; k += 32) {
        float h = __bfloat162float(g_hhi[0][r * HDIM + k]) +
                  __bfloat162float(g_hlo[0][r * HDIM + k]);
        s += h * Wout[k];
    }
#pragma unroll
    for (int o = 16; o; o >>= 1) s += __shfl_xor_sync(0xffffffffu, s, o);
    if (lane == 0) out[r] = s + bout[0];
}

// ---------------------------------------------------------------------------
extern "C" void kernel_launch(void* const* d_in, const int* in_sizes, int n_in,
                              void* d_out, int out_size) {
    (void)in_sizes; (void)n_in; (void)out_size;
    const float* x    = (const float*)d_in[0];
    const float* h0   = (const float*)d_in[1];
    const float* c0   = (const float*)d_in[2];
    const float* Wi   = (const float*)d_in[3];
    const float* bi   = (const float*)d_in[4];
    const float* Wf   = (const float*)d_in[5];
    const float* bf   = (const float*)d_in[6];
    const float* Wc   = (const float*)d_in[7];
    const float* bc   = (const float*)d_in[8];
    const float* Wo   = (const float*)d_in[9];
    const float* bo   = (const float*)d_in[10];
    const float* Wout = (const float*)d_in[11];
    const float* bout = (const float*)d_in[12];
    float* out = (float*)d_out;

    static int configured = 0;
    if (!configured) {
        cudaFuncSetAttribute(lstm_persistent,
                             cudaFuncAttributeMaxDynamicSharedMemorySize, SMEM_TOTAL);
        configured = 1;
    }

    init_state<<<(ROWS * HDIM + 255) / 256, 256>>>(h0, c0);
    repack<<<(NCTA * NCHUNK * 2048 + 255) / 256, 256>>>(Wi, Wf, Wc, Wo, bi, bf, bc, bo);
    lstm_persistent<<<NCTA, 256, SMEM_TOTAL>>>(x);
    out_final<<<32, 128>>>(Wout, bout, out);
}

// round 9
// speedup vs baseline: 1.4325x; 1.4325x over previous
#include <cuda_runtime.h>
#include <cuda_bf16.h>
#include <math.h>
#include <stdint.h>

// VanillaLSTM persistent kernel (sm_103 HMMA bf16-split), split-K warps.
// 96 CTAs x 512 threads (16 warps). Warps rw and rw+8 share rows [16rw,16rw+16):
// rw-half computes K-chunks 0-5, (rw+8)-half chunks 6-11; fp32 partials
// exchanged via SMEM + named barrier (64 threads!); each warp epilogues 4 of
// the 8 j-cols. Weights SMEM-resident (XOR-swizzled, pitch 128). Batched
// wait-all dataflow sync on per-(group,row-warp) counters, 16 rel/group/step.

#define ROWS 128
#define HDIM 768
#define SEQ  256
#define NCTA 96
#define NCHUNK 12

// smem layout (bytes)
#define WS_HI 0                  // 12 chunks * 32 rows * 128
#define WS_LO 49152
#define A_BASE 98304             // 16 warps * 2 bufs * 4096 (hi 2048 + lo 2048)
#define SMEM_TOTAL (A_BASE + 16 * 2 * 4096)   // 229376

__device__ __align__(16) __nv_bfloat16 g_hhi[2][ROWS * HDIM];
__device__ __align__(16) __nv_bfloat16 g_hlo[2][ROWS * HDIM];
__device__ __align__(16) float         g_c[ROWS * HDIM];
__device__ __align__(16) __nv_bfloat16 g_Bhi[NCTA * NCHUNK * 2048];  // pre-swizzled
__device__ __align__(16) __nv_bfloat16 g_Blo[NCTA * NCHUNK * 2048];
__device__ __align__(16) float2        g_wxb[NCTA * 32];
__device__ __align__(128) unsigned     g_ctr[NCHUNK * 8][32];  // (group, row-warp)

// ---------------------------------------------------------------------------
__device__ __forceinline__ uint32_t smem_u32(const void* p) {
    uint32_t a;
    asm("{ .reg .u64 t; cvta.to.shared.u64 t, %1; cvt.u32.u64 %0, t; }" : "=r"(a) : "l"(p));
    return a;
}
__device__ __forceinline__ void cpa16(uint32_t dst, const void* src) {
    asm volatile("cp.async.cg.shared.global [%0], [%1], 16;" :: "r"(dst), "l"(src) : "memory");
}
__device__ __forceinline__ void cp_commit() {
    asm volatile("cp.async.commit_group;" ::: "memory");
}
__device__ __forceinline__ void cp_wait1() {
    asm volatile("cp.async.wait_group 1;" ::: "memory");
}
__device__ __forceinline__ void cp_wait0() {
    asm volatile("cp.async.wait_group 0;" ::: "memory");
}
__device__ __forceinline__ void ldsm4(uint32_t* r, uint32_t addr) {
    asm volatile("ldmatrix.sync.aligned.m8n8.x4.shared.b16 {%0,%1,%2,%3}, [%4];"
                 : "=r"(r[0]), "=r"(r[1]), "=r"(r[2]), "=r"(r[3]) : "r"(addr));
}
__device__ __forceinline__ void mma_bf16(float* d, const uint32_t* a, uint32_t b0, uint32_t b1) {
    asm volatile(
        "mma.sync.aligned.m16n8k16.row.col.f32.bf16.bf16.f32 "
        "{%0,%1,%2,%3}, {%4,%5,%6,%7}, {%8,%9}, {%0,%1,%2,%3};"
        : "+f"(d[0]), "+f"(d[1]), "+f"(d[2]), "+f"(d[3])
        : "r"(a[0]), "r"(a[1]), "r"(a[2]), "r"(a[3]), "r"(b0), "r"(b1));
}

// ---------------------------------------------------------------------------
__global__ void init_state(const float* __restrict__ h0, const float* __restrict__ c0) {
    int i = blockIdx.x * 256 + threadIdx.x;
    if (i < NCHUNK * 8) g_ctr[i][0] = 0u;
    if (i < ROWS * HDIM) {
        float v = h0[i];
        __nv_bfloat16 hi = __float2bfloat16(v);
        g_hhi[0][i] = hi;
        g_hlo[0][i] = __float2bfloat16(v - __bfloat162float(hi));
        g_c[i] = c0[i];
    }
}

// ---------------------------------------------------------------------------
// Repack weights pre-swizzled: elem (blk, n, kl) ->
//   blk*2048 + n*64 + ((kl>>3) ^ (n&7))*8 + (kl&7)
__global__ void repack(const float* __restrict__ Wi, const float* __restrict__ Wf,
                       const float* __restrict__ Wc, const float* __restrict__ Wo,
                       const float* __restrict__ bi, const float* __restrict__ bf,
                       const float* __restrict__ bc, const float* __restrict__ bo) {
    int idx = blockIdx.x * 256 + threadIdx.x;
    const int TOT = NCTA * NCHUNK * 2048;
    if (idx < TOT) {
        int kl  = idx & 63;
        int n   = (idx >> 6) & 31;
        int blk = idx >> 11;
        int kc  = blk % NCHUNK;
        int nb  = blk / NCHUNK;
        int gate = n & 3;
        int j = nb * 8 + (n >> 2);
        const float* W = (gate == 0) ? Wi : (gate == 1) ? Wf : (gate == 2) ? Wc : Wo;
        float v = W[(1 + kc * 64 + kl) * HDIM + j];
        __nv_bfloat16 hi = __float2bfloat16(v);
        int dst = blk * 2048 + n * 64 + (((kl >> 3) ^ (n & 7)) << 3) + (kl & 7);
        g_Bhi[dst] = hi;
        g_Blo[dst] = __float2bfloat16(v - __bfloat162float(hi));
    }
    if (idx < NCTA * 32) {
        int n = idx & 31;
        int nb = idx >> 5;
        int gate = n & 3;
        int j = nb * 8 + (n >> 2);
        const float* W = (gate == 0) ? Wi : (gate == 1) ? Wf : (gate == 2) ? Wc : Wo;
        const float* B = (gate == 0) ? bi : (gate == 1) ? bf : (gate == 2) ? bc : bo;
        g_wxb[idx] = make_float2(W[j], B[j]);
    }
}

// ---------------------------------------------------------------------------
__global__ void __launch_bounds__(512, 1) lstm_persistent(const float* __restrict__ x) {
    extern __shared__ char smem[];
    const uint32_t sb = smem_u32(smem);
    const int tid = threadIdx.x;
    const int lane = tid & 31, wid = tid >> 5;
    const int rw = wid & 7;          // row-warp: rows [16rw, 16rw+16)
    const int hf = wid >> 3;         // K-half: chunks [6hf, 6hf+6)
    const int nb = blockIdx.x;

    // ---------------- prologue: stage W into smem (contiguous, pre-swizzled) --
    {
        const uint4* __restrict__ sh = ((const uint4*)g_Bhi) + nb * 3072;
        const uint4* __restrict__ sl = ((const uint4*)g_Blo) + nb * 3072;
        uint4* dh = (uint4*)(smem + WS_HI);
        uint4* dl = (uint4*)(smem + WS_LO);
        for (int i = tid; i < 3072; i += 512) { dh[i] = sh[i]; dl[i] = sl[i]; }
    }
    __syncthreads();

    const uint32_t abase = sb + A_BASE + (uint32_t)wid * 8192;  // 2 bufs x 4096

    // ldsm lane constants (XOR swizzle, pitch 128; both xor keys reduce to li)
    const int sel = lane >> 3, li = lane & 7;
    const int hsA = sel >> 1, hsB = sel & 1;
    const uint32_t aoffrow = (uint32_t)((li + (sel & 1) * 8) * 128);
    const uint32_t boffrow = (uint32_t)((li + (sel >> 1) * 8) * 128);

    // epilogue constants
    const int my_row = rw * 16 + (lane >> 2) + (lane & 1) * 8;
    const float* __restrict__ xrow = x + (my_row >> 1) * 512 + (my_row & 1);
    const int ntK = (hf == 0) ? 0 : 2;    // kept n-tiles
    const int ntS = 2 - ntK;              // sent n-tiles

    // registers: wxb + cell state for kept n-tiles
    float2 wxi[2], wxf[2], wxc[2], wxo[2];
    float  creg[2];
    {
        const float2* __restrict__ wxbp = g_wxb + nb * 32;
#pragma unroll
        for (int q = 0; q < 2; ++q) {
            int jl = (ntK + q) * 2 + ((lane & 3) >> 1);
            wxi[q] = wxbp[4 * jl + 0];
            wxf[q] = wxbp[4 * jl + 1];
            wxc[q] = wxbp[4 * jl + 2];
            wxo[q] = wxbp[4 * jl + 3];
            creg[q] = g_c[my_row * HDIM + nb * 8 + jl];
        }
    }

    // sync: lane g (<12) polls counter (g, rw); release (nb>>3, rw)
    const unsigned* __restrict__ pollp =
        (lane < NCHUNK) ? &g_ctr[lane * 8 + rw][0] : &g_ctr[0][0];
    unsigned* __restrict__ relp = &g_ctr[(nb >> 3) * 8 + rw][0];

    for (int t = 0; t < SEQ; ++t) {
        const int par = t & 1;
        const __nv_bfloat16* __restrict__ hhi = g_hhi[par];
        const __nv_bfloat16* __restrict__ hlo = g_hlo[par];
        __nv_bfloat16* __restrict__ ohi = g_hhi[par ^ 1];
        __nv_bfloat16* __restrict__ olo = g_hlo[par ^ 1];

        // batched wait: all 12 groups for this row-warp (RAW for own chunks,
        // WAR cover for all readers of our output cells)
        if (t > 0) {
            const unsigned tgt = 16u * (unsigned)t;
            for (;;) {
                unsigned v = tgt;
                if (lane < NCHUNK) {
                    asm volatile("ld.acquire.gpu.global.u32 %0, [%1];"
                                 : "=r"(v) : "l"(pollp) : "memory");
                }
                if (__all_sync(0xffffffffu, v >= tgt)) break;
            }
        }
        __syncwarp();

        float d[4][4];
#pragma unroll
        for (int i = 0; i < 4; i++)
#pragma unroll
            for (int k = 0; k < 4; k++) d[i][k] = 0.f;

        // per-warp A staging: 16 rows x 64 k (hi+lo), XOR swizzle, buffer l%2
        auto issue = [&](int l) {
            const int g = hf * 6 + l;
            const uint32_t bufs = abase + (uint32_t)(l & 1) * 4096;
#pragma unroll
            for (int i = 0; i < 4; ++i) {
                int o = lane * 4 + i;            // 0..127
                int row = o >> 3, seg = o & 7;
                uint32_t dst = bufs + (uint32_t)(row * 128 + ((seg ^ (row & 7)) << 4));
                const int so = (rw * 16 + row) * HDIM + g * 64 + seg * 8;
                cpa16(dst, hhi + so);
                cpa16(dst + 2048, hlo + so);
            }
            cp_commit();
        };

        issue(0);
        issue(1);

#pragma unroll
        for (int l = 0; l < 6; ++l) {
            if (l < 5) cp_wait1(); else cp_wait0();
            __syncwarp();
            const int g = hf * 6 + l;
            const uint32_t abuf = abase + (uint32_t)(l & 1) * 4096;
            const uint32_t whi = sb + WS_HI + (uint32_t)g * 4096;
            const uint32_t wlo = sb + WS_LO + (uint32_t)g * 4096;
#pragma unroll
            for (int ks = 0; ks < 4; ++ks) {
                const uint32_t asw = (uint32_t)((((ks << 1) | hsA) ^ li) << 4);
                const uint32_t bsw = (uint32_t)((((ks << 1) | hsB) ^ li) << 4);
                uint32_t ah[4], al[4];
                ldsm4(ah, abuf + aoffrow + asw);
                ldsm4(al, abuf + 2048 + aoffrow + asw);
#pragma unroll
                for (int p = 0; p < 2; ++p) {
                    uint32_t bh[4], bl[4];
                    const uint32_t bo2 = boffrow + (uint32_t)(p * 2048) + bsw;
                    ldsm4(bh, whi + bo2);
                    ldsm4(bl, wlo + bo2);
                    mma_bf16(d[2 * p],     ah, bh[0], bh[1]);
                    mma_bf16(d[2 * p],     ah, bl[0], bl[1]);
                    mma_bf16(d[2 * p],     al, bh[0], bh[1]);
                    mma_bf16(d[2 * p + 1], ah, bh[2], bh[3]);
                    mma_bf16(d[2 * p + 1], ah, bl[2], bl[3]);
                    mma_bf16(d[2 * p + 1], al, bh[2], bh[3]);
                }
            }
            __syncwarp();
            if (l + 2 < 6) issue(l + 2);
        }

        // ---------------- split-K partial exchange (warp pair rw, rw+8) -------
        // NOTE: named barrier count = 64 (2 warps), ids 1..8
        {
            float* ex = (float*)(smem + A_BASE + wid * 8192 + lane * 32);
#pragma unroll
            for (int k = 0; k < 4; ++k) { ex[k] = d[ntS][k]; ex[4 + k] = d[ntS + 1][k]; }
            asm volatile("bar.sync %0, 64;" :: "r"(1 + rw) : "memory");
            const float* px = (const float*)(smem + A_BASE + (wid ^ 8) * 8192 + lane * 32);
#pragma unroll
            for (int k = 0; k < 4; ++k) { d[ntK][k] += px[k]; d[ntK + 1][k] += px[4 + k]; }
            asm volatile("bar.sync %0, 64;" :: "r"(1 + rw) : "memory");
        }

        // ---------------- fused LSTM epilogue (kept n-tiles) ------------------
        const float xv = xrow[2 * t];
#pragma unroll
        for (int q = 0; q < 2; ++q) {
            const int nt = ntK + q;
            const int jl = nt * 2 + ((lane & 3) >> 1);
            float p0 = __shfl_xor_sync(0xffffffffu, d[nt][0], 1);
            float p1 = __shfl_xor_sync(0xffffffffu, d[nt][1], 1);
            float p2 = __shfl_xor_sync(0xffffffffu, d[nt][2], 1);
            float p3 = __shfl_xor_sync(0xffffffffu, d[nt][3], 1);
            float gi, gf, gc, go;
            if (!(lane & 1)) { gi = d[nt][0]; gf = d[nt][1]; gc = p0; go = p1; }
            else             { gi = p2;       gf = p3;       gc = d[nt][2]; go = d[nt][3]; }
            float pi = gi + xv * wxi[q].x + wxi[q].y;
            float pf = gf + xv * wxf[q].x + wxf[q].y;
            float pc = gc + xv * wxc[q].x + wxc[q].y;
            float po = go + xv * wxo[q].x + wxo[q].y;
            float ig = __fdividef(1.f, 1.f + __expf(-pi));
            float fg = __fdividef(1.f, 1.f + __expf(-pf));
            float thc = 1.f - __fdividef(2.f, 1.f + __expf(2.f * pc));
            float cn = fg * creg[q] + ig * thc;
            float thn = 1.f - __fdividef(2.f, 1.f + __expf(2.f * cn));
            float hn = po * thn;            // no sigmoid on output gate
            creg[q] = cn;
            const int idx = my_row * HDIM + nb * 8 + jl;
            __nv_bfloat16 hi = __float2bfloat16(hn);
            ohi[idx] = hi;
            olo[idx] = __float2bfloat16(hn - __bfloat162float(hi));
        }

        // publish (release orders prior stores); both warps of pair increment
        if (t + 1 < SEQ) {
            __syncwarp();
            if (lane == 0) {
                asm volatile("red.release.gpu.global.add.u32 [%0], %1;"
                             :: "l"(relp), "r"(1u) : "memory");
            }
        }
    }
}

// ---------------------------------------------------------------------------
__global__ void out_final(const float* __restrict__ Wout,
                          const float* __restrict__ bout,
                          float* __restrict__ out) {
    int gtid = blockIdx.x * 128 + threadIdx.x;
    int r = gtid >> 5, lane = gtid & 31;
    float s = 0.f;
    for (int k = lane; k < HDIM; k += 32) {
        float h = __bfloat162float(g_hhi[0][r * HDIM + k]) +
                  __bfloat162float(g_hlo[0][r * HDIM + k]);
        s += h * Wout[k];
    }
#pragma unroll
    for (int o = 16; o; o >>= 1) s += __shfl_xor_sync(0xffffffffu, s, o);
    if (lane == 0) out[r] = s + bout[0];
}

// ---------------------------------------------------------------------------
extern "C" void kernel_launch(void* const* d_in, const int* in_sizes, int n_in,
                              void* d_out, int out_size) {
    (void)in_sizes; (void)n_in; (void)out_size;
    const float* x    = (const float*)d_in[0];
    const float* h0   = (const float*)d_in[1];
    const float* c0   = (const float*)d_in[2];
    const float* Wi   = (const float*)d_in[3];
    const float* bi   = (const float*)d_in[4];
    const float* Wf   = (const float*)d_in[5];
    const float* bf   = (const float*)d_in[6];
    const float* Wc   = (const float*)d_in[7];
    const float* bc   = (const float*)d_in[8];
    const float* Wo   = (const float*)d_in[9];
    const float* bo   = (const float*)d_in[10];
    const float* Wout = (const float*)d_in[11];
    const float* bout = (const float*)d_in[12];
    float* out = (float*)d_out;

    static int configured = 0;
    if (!configured) {
        cudaFuncSetAttribute(lstm_persistent,
                             cudaFuncAttributeMaxDynamicSharedMemorySize, SMEM_TOTAL);
        configured = 1;
    }

    init_state<<<(ROWS * HDIM + 255) / 256, 256>>>(h0, c0);
    repack<<<(NCTA * NCHUNK * 2048 + 255) / 256, 256>>>(Wi, Wf, Wc, Wo, bi, bf, bc, bo);
    lstm_persistent<<<NCTA, 512, SMEM_TOTAL>>>(x);
    out_final<<<32, 128>>>(Wout, bout, out);
}

// round 10
// speedup vs baseline: 1.6280x; 1.1365x over previous
#include <cuda_runtime.h>
#include <cuda_fp16.h>
#include <math.h>
#include <stdint.h>

// VanillaLSTM persistent kernel (sm_103 HMMA fp16 2-MMA), split-K warps.
// 96 CTAs x 512 threads. h stored fp16 (single); W split fp16 hi + scaled lo
// (Wlo*4096, separate fp32 accumulator, combined at epilogue: d0 + d1*2^-12).
// Warps rw / rw+8 split K (chunks 0-5 / 6-11), partials merged via SMEM +
// 64-thread named barrier. Depth-3 cp.async A pipeline. Dataflow sync via
// per-(group,row-warp) counters; warp 0 polls L2, publishes to SMEM flag.

#define ROWS 128
#define HDIM 768
#define SEQ  256
#define NCTA 96
#define NCHUNK 12

// smem layout (bytes)
#define WS_HI 0                  // 12 chunks * 32 rows * 128B (fp16)
#define WS_LO 49152
#define A_BASE 98304             // 16 warps * 3 bufs * 2048
#define FLAG_OFF (A_BASE + 16 * 3 * 2048)     // 196608
#define SMEM_TOTAL (FLAG_OFF + 128)           // 196736

__device__ __align__(16) __half        g_h[2][ROWS * HDIM];
__device__ __align__(16) float         g_c[ROWS * HDIM];
__device__ __align__(16) __half        g_Whi[NCTA * NCHUNK * 2048];  // pre-swizzled
__device__ __align__(16) __half        g_Wlo[NCTA * NCHUNK * 2048];  // (W-Whi)*4096
__device__ __align__(16) float2        g_wxb[NCTA * 32];
__device__ __align__(128) unsigned     g_ctr[NCHUNK * 8][32];  // (group, row-warp)

// ---------------------------------------------------------------------------
__device__ __forceinline__ uint32_t smem_u32(const void* p) {
    uint32_t a;
    asm("{ .reg .u64 t; cvta.to.shared.u64 t, %1; cvt.u32.u64 %0, t; }" : "=r"(a) : "l"(p));
    return a;
}
__device__ __forceinline__ void cpa16(uint32_t dst, const void* src) {
    asm volatile("cp.async.cg.shared.global [%0], [%1], 16;" :: "r"(dst), "l"(src) : "memory");
}
__device__ __forceinline__ void cp_commit() {
    asm volatile("cp.async.commit_group;" ::: "memory");
}
__device__ __forceinline__ void cp_wait2() {
    asm volatile("cp.async.wait_group 2;" ::: "memory");
}
__device__ __forceinline__ void cp_wait1() {
    asm volatile("cp.async.wait_group 1;" ::: "memory");
}
__device__ __forceinline__ void cp_wait0() {
    asm volatile("cp.async.wait_group 0;" ::: "memory");
}
__device__ __forceinline__ void ldsm4(uint32_t* r, uint32_t addr) {
    asm volatile("ldmatrix.sync.aligned.m8n8.x4.shared.b16 {%0,%1,%2,%3}, [%4];"
                 : "=r"(r[0]), "=r"(r[1]), "=r"(r[2]), "=r"(r[3]) : "r"(addr));
}
__device__ __forceinline__ void mma_f16(float* d, const uint32_t* a, uint32_t b0, uint32_t b1) {
    asm volatile(
        "mma.sync.aligned.m16n8k16.row.col.f32.f16.f16.f32 "
        "{%0,%1,%2,%3}, {%4,%5,%6,%7}, {%8,%9}, {%0,%1,%2,%3};"
        : "+f"(d[0]), "+f"(d[1]), "+f"(d[2]), "+f"(d[3])
        : "r"(a[0]), "r"(a[1]), "r"(a[2]), "r"(a[3]), "r"(b0), "r"(b1));
}

// ---------------------------------------------------------------------------
__global__ void init_state(const float* __restrict__ h0, const float* __restrict__ c0) {
    int i = blockIdx.x * 256 + threadIdx.x;
    if (i < NCHUNK * 8) g_ctr[i][0] = 0u;
    if (i < ROWS * HDIM) {
        g_h[0][i] = __float2half(h0[i]);
        g_c[i] = c0[i];
    }
}

// ---------------------------------------------------------------------------
// Repack weights pre-swizzled fp16: elem (blk, n, kl) ->
//   blk*2048 + n*64 + ((kl>>3) ^ (n&7))*8 + (kl&7);  Wlo scaled by 4096.
__global__ void repack(const float* __restrict__ Wi, const float* __restrict__ Wf,
                       const float* __restrict__ Wc, const float* __restrict__ Wo,
                       const float* __restrict__ bi, const float* __restrict__ bf,
                       const float* __restrict__ bc, const float* __restrict__ bo) {
    int idx = blockIdx.x * 256 + threadIdx.x;
    const int TOT = NCTA * NCHUNK * 2048;
    if (idx < TOT) {
        int kl  = idx & 63;
        int n   = (idx >> 6) & 31;
        int blk = idx >> 11;
        int kc  = blk % NCHUNK;
        int nb  = blk / NCHUNK;
        int gate = n & 3;
        int j = nb * 8 + (n >> 2);
        const float* W = (gate == 0) ? Wi : (gate == 1) ? Wf : (gate == 2) ? Wc : Wo;
        float v = W[(1 + kc * 64 + kl) * HDIM + j];
        __half hi = __float2half(v);
        int dst = blk * 2048 + n * 64 + (((kl >> 3) ^ (n & 7)) << 3) + (kl & 7);
        g_Whi[dst] = hi;
        g_Wlo[dst] = __float2half((v - __half2float(hi)) * 4096.f);
    }
    if (idx < NCTA * 32) {
        int n = idx & 31;
        int nb = idx >> 5;
        int gate = n & 3;
        int j = nb * 8 + (n >> 2);
        const float* W = (gate == 0) ? Wi : (gate == 1) ? Wf : (gate == 2) ? Wc : Wo;
        const float* B = (gate == 0) ? bi : (gate == 1) ? bf : (gate == 2) ? bc : bo;
        g_wxb[idx] = make_float2(W[j], B[j]);
    }
}

// ---------------------------------------------------------------------------
__global__ void __launch_bounds__(512, 1) lstm_persistent(const float* __restrict__ x) {
    extern __shared__ char smem[];
    const uint32_t sb = smem_u32(smem);
    const int tid = threadIdx.x;
    const int lane = tid & 31, wid = tid >> 5;
    const int rw = wid & 7;          // row-warp: rows [16rw, 16rw+16)
    const int hf = wid >> 3;         // K-half: chunks [6hf, 6hf+6)
    const int nb = blockIdx.x;
    const uint32_t flag_addr = sb + FLAG_OFF;

    // ---------------- prologue: stage W into smem (contiguous, pre-swizzled) --
    {
        const uint4* __restrict__ sh = ((const uint4*)g_Whi) + nb * 3072;
        const uint4* __restrict__ sl = ((const uint4*)g_Wlo) + nb * 3072;
        uint4* dh = (uint4*)(smem + WS_HI);
        uint4* dl = (uint4*)(smem + WS_LO);
        for (int i = tid; i < 3072; i += 512) { dh[i] = sh[i]; dl[i] = sl[i]; }
        if (tid == 0) *(volatile unsigned*)(smem + FLAG_OFF) = 0u;
    }
    __syncthreads();

    const uint32_t abase = sb + A_BASE + (uint32_t)wid * 6144;  // 3 bufs x 2048

    // ldsm lane constants (XOR swizzle, pitch 128)
    const int sel = lane >> 3, li = lane & 7;
    const int hsA = sel >> 1, hsB = sel & 1;
    const uint32_t aoffrow = (uint32_t)((li + (sel & 1) * 8) * 128);
    const uint32_t boffrow = (uint32_t)((li + (sel >> 1) * 8) * 128);

    // epilogue constants
    const int my_row = rw * 16 + (lane >> 2) + (lane & 1) * 8;
    const float* __restrict__ xrow = x + (my_row >> 1) * 512 + (my_row & 1);
    const int ntK = (hf == 0) ? 0 : 2;    // kept n-tiles
    const int ntS = 2 - ntK;              // sent n-tiles

    // registers: wxb + cell state for kept n-tiles
    float2 wxi[2], wxf[2], wxc[2], wxo[2];
    float  creg[2];
    {
        const float2* __restrict__ wxbp = g_wxb + nb * 32;
#pragma unroll
        for (int q = 0; q < 2; ++q) {
            int jl = (ntK + q) * 2 + ((lane & 3) >> 1);
            wxi[q] = wxbp[4 * jl + 0];
            wxf[q] = wxbp[4 * jl + 1];
            wxc[q] = wxbp[4 * jl + 2];
            wxo[q] = wxbp[4 * jl + 3];
            creg[q] = g_c[my_row * HDIM + nb * 8 + jl];
        }
    }

    // sync: warp 0 polls counters (lane g<12 -> group g, row-warp = lane&7? no:
    // warp 0 must cover ALL row-warps; use min over rw by polling (g, rw) for
    // all rw via 12 lanes x per-group... simplest exact: lane<12 polls group
    // lane with rw index = min? Counters are per (group, rw): all rw of same
    // group advance together only if all 16 warps released. To cover WAR for
    // every warp we need min over all 96 counters. Instead: keep per-warp
    // correctness by having warp 0 poll ALL 96 counters: lane l polls 3
    // counters (l, l+32, l+64) of the 96 = 12 groups x 8 rw.
    unsigned* __restrict__ relp = &g_ctr[(nb >> 3) * 8 + rw][0];
    const int c0i = lane, c1i = lane + 32, c2i = lane + 64;
    const unsigned* __restrict__ poll0 = &g_ctr[c0i % 12 * 8 + c0i / 12][0];
    const unsigned* __restrict__ poll1 = &g_ctr[c1i % 12 * 8 + c1i / 12][0];
    const unsigned* __restrict__ poll2 = &g_ctr[c2i % 12 * 8 + c2i / 12][0];

    for (int t = 0; t < SEQ; ++t) {
        const int par = t & 1;
        const __half* __restrict__ hin = g_h[par];
        __half* __restrict__ hout = g_h[par ^ 1];

        // ---- dataflow wait ----
        if (t > 0) {
            const unsigned tgt = 16u * (unsigned)t;
            if (wid == 0) {
                for (;;) {
                    unsigned v0, v1, v2;
                    asm volatile("ld.acquire.gpu.global.u32 %0, [%1];" : "=r"(v0) : "l"(poll0) : "memory");
                    asm volatile("ld.acquire.gpu.global.u32 %0, [%1];" : "=r"(v1) : "l"(poll1) : "memory");
                    asm volatile("ld.acquire.gpu.global.u32 %0, [%1];" : "=r"(v2) : "l"(poll2) : "memory");
                    bool ok = (v0 >= tgt) && (v1 >= tgt) && (v2 >= tgt);
                    if (__all_sync(0xffffffffu, ok)) break;
                }
                if (lane == 0) {
                    asm volatile("st.release.cta.shared.u32 [%0], %1;"
                                 :: "r"(flag_addr), "r"((unsigned)t) : "memory");
                }
                __syncwarp();
            } else {
                unsigned v;
                do {
                    asm volatile("ld.acquire.cta.shared.u32 %0, [%1];"
                                 : "=r"(v) : "r"(flag_addr) : "memory");
                } while (v < (unsigned)t);
            }
        }
        __syncwarp();

        float d0[4][4], d1[4][4];
#pragma unroll
        for (int i = 0; i < 4; i++)
#pragma unroll
            for (int k = 0; k < 4; k++) { d0[i][k] = 0.f; d1[i][k] = 0.f; }

        // per-warp A staging: 16 rows x 64 k fp16, XOR swizzle, buffer l%3
        auto issue = [&](int l) {
            const int g = hf * 6 + l;
            const uint32_t bufs = abase + (uint32_t)(l % 3) * 2048;
#pragma unroll
            for (int i = 0; i < 4; ++i) {
                int o = lane * 4 + i;            // 0..127
                int row = o >> 3, seg = o & 7;
                uint32_t dst = bufs + (uint32_t)(row * 128 + ((seg ^ (row & 7)) << 4));
                cpa16(dst, hin + (rw * 16 + row) * HDIM + g * 64 + seg * 8);
            }
            cp_commit();
        };

        issue(0); issue(1); issue(2);

#pragma unroll
        for (int l = 0; l < 6; ++l) {
            if (l < 4)      cp_wait2();
            else if (l == 4) cp_wait1();
            else             cp_wait0();
            __syncwarp();
            const int g = hf * 6 + l;
            const uint32_t abuf = abase + (uint32_t)(l % 3) * 2048;
            const uint32_t whi = sb + WS_HI + (uint32_t)g * 4096;
            const uint32_t wlo = sb + WS_LO + (uint32_t)g * 4096;
#pragma unroll
            for (int ks = 0; ks < 4; ++ks) {
                const uint32_t asw = (uint32_t)((((ks << 1) | hsA) ^ li) << 4);
                const uint32_t bsw = (uint32_t)((((ks << 1) | hsB) ^ li) << 4);
                uint32_t a[4];
                ldsm4(a, abuf + aoffrow + asw);
#pragma unroll
                for (int p = 0; p < 2; ++p) {
                    uint32_t bh[4], bl[4];
                    const uint32_t bo2 = boffrow + (uint32_t)(p * 2048) + bsw;
                    ldsm4(bh, whi + bo2);
                    ldsm4(bl, wlo + bo2);
                    mma_f16(d0[2 * p],     a, bh[0], bh[1]);
                    mma_f16(d0[2 * p + 1], a, bh[2], bh[3]);
                    mma_f16(d1[2 * p],     a, bl[0], bl[1]);
                    mma_f16(d1[2 * p + 1], a, bl[2], bl[3]);
                }
            }
            __syncwarp();
            if (l + 3 < 6) issue(l + 3);
        }

        // combine hi + scaled lo accumulators
        const float SC = 1.f / 4096.f;
        float dc[4][4];
#pragma unroll
        for (int i = 0; i < 4; i++)
#pragma unroll
            for (int k = 0; k < 4; k++) dc[i][k] = d0[i][k] + d1[i][k] * SC;

        // ---------------- split-K partial exchange (warp pair rw, rw+8) -------
        {
            float* ex = (float*)(smem + A_BASE + wid * 6144 + lane * 32);
#pragma unroll
            for (int k = 0; k < 4; ++k) { ex[k] = dc[ntS][k]; ex[4 + k] = dc[ntS + 1][k]; }
            asm volatile("bar.sync %0, 64;" :: "r"(1 + rw) : "memory");
            const float* px = (const float*)(smem + A_BASE + (wid ^ 8) * 6144 + lane * 32);
#pragma unroll
            for (int k = 0; k < 4; ++k) { dc[ntK][k] += px[k]; dc[ntK + 1][k] += px[4 + k]; }
            asm volatile("bar.sync %0, 64;" :: "r"(1 + rw) : "memory");
        }

        // ---------------- fused LSTM epilogue (kept n-tiles) ------------------
        const float xv = xrow[2 * t];
#pragma unroll
        for (int q = 0; q < 2; ++q) {
            const int nt = ntK + q;
            const int jl = nt * 2 + ((lane & 3) >> 1);
            float p0 = __shfl_xor_sync(0xffffffffu, dc[nt][0], 1);
            float p1 = __shfl_xor_sync(0xffffffffu, dc[nt][1], 1);
            float p2 = __shfl_xor_sync(0xffffffffu, dc[nt][2], 1);
            float p3 = __shfl_xor_sync(0xffffffffu, dc[nt][3], 1);
            float gi, gf, gc, go;
            if (!(lane & 1)) { gi = dc[nt][0]; gf = dc[nt][1]; gc = p0; go = p1; }
            else             { gi = p2;        gf = p3;        gc = dc[nt][2]; go = dc[nt][3]; }
            float pi = gi + xv * wxi[q].x + wxi[q].y;
            float pf = gf + xv * wxf[q].x + wxf[q].y;
            float pc = gc + xv * wxc[q].x + wxc[q].y;
            float po = go + xv * wxo[q].x + wxo[q].y;
            float ig = __fdividef(1.f, 1.f + __expf(-pi));
            float fg = __fdividef(1.f, 1.f + __expf(-pf));
            float thc = 1.f - __fdividef(2.f, 1.f + __expf(2.f * pc));
            float cn = fg * creg[q] + ig * thc;
            float thn = 1.f - __fdividef(2.f, 1.f + __expf(2.f * cn));
            float hn = po * thn;            // no sigmoid on output gate
            creg[q] = cn;
            hout[my_row * HDIM + nb * 8 + jl] = __float2half(hn);
        }

        // publish (release orders prior stores)
        if (t + 1 < SEQ) {
            __syncwarp();
            if (lane == 0) {
                asm volatile("red.release.gpu.global.add.u32 [%0], %1;"
                             :: "l"(relp), "r"(1u) : "memory");
            }
        }
    }
}

// ---------------------------------------------------------------------------
__global__ void out_final(const float* __restrict__ Wout,
                          const float* __restrict__ bout,
                          float* __restrict__ out) {
    int gtid = blockIdx.x * 128 + threadIdx.x;
    int r = gtid >> 5, lane = gtid & 31;
    float s = 0.f;
    for (int k = lane; k < HDIM; k += 32)
        s += __half2float(g_h[0][r * HDIM + k]) * Wout[k];
#pragma unroll
    for (int o = 16; o; o >>= 1) s += __shfl_xor_sync(0xffffffffu, s, o);
    if (lane == 0) out[r] = s + bout[0];
}

// ---------------------------------------------------------------------------
extern "C" void kernel_launch(void* const* d_in, const int* in_sizes, int n_in,
                              void* d_out, int out_size) {
    (void)in_sizes; (void)n_in; (void)out_size;
    const float* x    = (const float*)d_in[0];
    const float* h0   = (const float*)d_in[1];
    const float* c0   = (const float*)d_in[2];
    const float* Wi   = (const float*)d_in[3];
    const float* bi   = (const float*)d_in[4];
    const float* Wf   = (const float*)d_in[5];
    const float* bf   = (const float*)d_in[6];
    const float* Wc   = (const float*)d_in[7];
    const float* bc   = (const float*)d_in[8];
    const float* Wo   = (const float*)d_in[9];
    const float* bo   = (const float*)d_in[10];
    const float* Wout = (const float*)d_in[11];
    const float* bout = (const float*)d_in[12];
    float* out = (float*)d_out;

    static int configured = 0;
    if (!configured) {
        cudaFuncSetAttribute(lstm_persistent,
                             cudaFuncAttributeMaxDynamicSharedMemorySize, SMEM_TOTAL);
        configured = 1;
    }

    init_state<<<(ROWS * HDIM + 255) / 256, 256>>>(h0, c0);
    repack<<<(NCTA * NCHUNK * 2048 + 255) / 256, 256>>>(Wi, Wf, Wc, Wo, bi, bf, bc, bo);
    lstm_persistent<<<NCTA, 512, SMEM_TOTAL>>>(x);
    out_final<<<32, 128>>>(Wout, bout, out);
}

// round 11
// speedup vs baseline: 1.8834x; 1.1569x over previous
#include <cuda_runtime.h>
#include <cuda_fp16.h>
#include <math.h>
#include <stdint.h>

// VanillaLSTM persistent kernel (sm_103 HMMA fp16 single-W), split-K warps.
// 96 CTAs x 512 threads. h fp16, W fp16 (single precision level, no lo term):
// R10 measured 4e-5 rel_err with exact W; fp16 W adds ~1e-4 — margin vs 1e-3.
// Warps rw / rw+8 split K (chunks 0-5 / 6-11), partials merged via SMEM +
// 64-thread named barrier. Depth-3 cp.async A pipeline. Dataflow sync via
// per-(group,row-warp) counters; warp 0 polls all 96 in L2, SMEM flag fanout.

#define ROWS 128
#define HDIM 768
#define SEQ  256
#define NCTA 96
#define NCHUNK 12

// smem layout (bytes)
#define WS_BASE 0                // 12 chunks * 32 rows * 128B (fp16) = 48KB
#define A_BASE 49152             // 16 warps * 3 bufs * 2048 = 96KB
#define FLAG_OFF (A_BASE + 16 * 3 * 2048)     // 147456
#define SMEM_TOTAL (FLAG_OFF + 128)           // 147584

__device__ __align__(16) __half        g_h[2][ROWS * HDIM];
__device__ __align__(16) float         g_c[ROWS * HDIM];
__device__ __align__(16) __half        g_W[NCTA * NCHUNK * 2048];   // pre-swizzled
__device__ __align__(16) float2        g_wxb[NCTA * 32];
__device__ __align__(128) unsigned     g_ctr[NCHUNK * 8][32];  // (group, row-warp)

// ---------------------------------------------------------------------------
__device__ __forceinline__ uint32_t smem_u32(const void* p) {
    uint32_t a;
    asm("{ .reg .u64 t; cvta.to.shared.u64 t, %1; cvt.u32.u64 %0, t; }" : "=r"(a) : "l"(p));
    return a;
}
__device__ __forceinline__ void cpa16(uint32_t dst, const void* src) {
    asm volatile("cp.async.cg.shared.global [%0], [%1], 16;" :: "r"(dst), "l"(src) : "memory");
}
__device__ __forceinline__ void cp_commit() {
    asm volatile("cp.async.commit_group;" ::: "memory");
}
__device__ __forceinline__ void cp_wait2() {
    asm volatile("cp.async.wait_group 2;" ::: "memory");
}
__device__ __forceinline__ void cp_wait1() {
    asm volatile("cp.async.wait_group 1;" ::: "memory");
}
__device__ __forceinline__ void cp_wait0() {
    asm volatile("cp.async.wait_group 0;" ::: "memory");
}
__device__ __forceinline__ void ldsm4(uint32_t* r, uint32_t addr) {
    asm volatile("ldmatrix.sync.aligned.m8n8.x4.shared.b16 {%0,%1,%2,%3}, [%4];"
                 : "=r"(r[0]), "=r"(r[1]), "=r"(r[2]), "=r"(r[3]) : "r"(addr));
}
__device__ __forceinline__ void mma_f16(float* d, const uint32_t* a, uint32_t b0, uint32_t b1) {
    asm volatile(
        "mma.sync.aligned.m16n8k16.row.col.f32.f16.f16.f32 "
        "{%0,%1,%2,%3}, {%4,%5,%6,%7}, {%8,%9}, {%0,%1,%2,%3};"
        : "+f"(d[0]), "+f"(d[1]), "+f"(d[2]), "+f"(d[3])
        : "r"(a[0]), "r"(a[1]), "r"(a[2]), "r"(a[3]), "r"(b0), "r"(b1));
}

// ---------------------------------------------------------------------------
__global__ void init_state(const float* __restrict__ h0, const float* __restrict__ c0) {
    int i = blockIdx.x * 256 + threadIdx.x;
    if (i < NCHUNK * 8) g_ctr[i][0] = 0u;
    if (i < ROWS * HDIM) {
        g_h[0][i] = __float2half(h0[i]);
        g_c[i] = c0[i];
    }
}

// ---------------------------------------------------------------------------
// Repack weights pre-swizzled fp16: elem (blk, n, kl) ->
//   blk*2048 + n*64 + ((kl>>3) ^ (n&7))*8 + (kl&7)
__global__ void repack(const float* __restrict__ Wi, const float* __restrict__ Wf,
                       const float* __restrict__ Wc, const float* __restrict__ Wo,
                       const float* __restrict__ bi, const float* __restrict__ bf,
                       const float* __restrict__ bc, const float* __restrict__ bo) {
    int idx = blockIdx.x * 256 + threadIdx.x;
    const int TOT = NCTA * NCHUNK * 2048;
    if (idx < TOT) {
        int kl  = idx & 63;
        int n   = (idx >> 6) & 31;
        int blk = idx >> 11;
        int kc  = blk % NCHUNK;
        int nb  = blk / NCHUNK;
        int gate = n & 3;
        int j = nb * 8 + (n >> 2);
        const float* W = (gate == 0) ? Wi : (gate == 1) ? Wf : (gate == 2) ? Wc : Wo;
        float v = W[(1 + kc * 64 + kl) * HDIM + j];
        int dst = blk * 2048 + n * 64 + (((kl >> 3) ^ (n & 7)) << 3) + (kl & 7);
        g_W[dst] = __float2half(v);
    }
    if (idx < NCTA * 32) {
        int n = idx & 31;
        int nb = idx >> 5;
        int gate = n & 3;
        int j = nb * 8 + (n >> 2);
        const float* W = (gate == 0) ? Wi : (gate == 1) ? Wf : (gate == 2) ? Wc : Wo;
        const float* B = (gate == 0) ? bi : (gate == 1) ? bf : (gate == 2) ? bc : bo;
        g_wxb[idx] = make_float2(W[j], B[j]);
    }
}

// ---------------------------------------------------------------------------
__global__ void __launch_bounds__(512, 1) lstm_persistent(const float* __restrict__ x) {
    extern __shared__ char smem[];
    const uint32_t sb = smem_u32(smem);
    const int tid = threadIdx.x;
    const int lane = tid & 31, wid = tid >> 5;
    const int rw = wid & 7;          // row-warp: rows [16rw, 16rw+16)
    const int hf = wid >> 3;         // K-half: chunks [6hf, 6hf+6)
    const int nb = blockIdx.x;
    const uint32_t flag_addr = sb + FLAG_OFF;

    // ---------------- prologue: stage W into smem (contiguous, pre-swizzled) --
    {
        const uint4* __restrict__ sw = ((const uint4*)g_W) + nb * 3072;
        uint4* dw = (uint4*)(smem + WS_BASE);
        for (int i = tid; i < 3072; i += 512) dw[i] = sw[i];
        if (tid == 0) *(volatile unsigned*)(smem + FLAG_OFF) = 0u;
    }
    __syncthreads();

    const uint32_t abase = sb + A_BASE + (uint32_t)wid * 6144;  // 3 bufs x 2048

    // ldsm lane constants (XOR swizzle, pitch 128)
    const int sel = lane >> 3, li = lane & 7;
    const int hsA = sel >> 1, hsB = sel & 1;
    const uint32_t aoffrow = (uint32_t)((li + (sel & 1) * 8) * 128);
    const uint32_t boffrow = (uint32_t)((li + (sel >> 1) * 8) * 128);

    // epilogue constants
    const int my_row = rw * 16 + (lane >> 2) + (lane & 1) * 8;
    const float* __restrict__ xrow = x + (my_row >> 1) * 512 + (my_row & 1);
    const int ntK = (hf == 0) ? 0 : 2;    // kept n-tiles
    const int ntS = 2 - ntK;              // sent n-tiles

    // registers: wxb + cell state for kept n-tiles
    float2 wxi[2], wxf[2], wxc[2], wxo[2];
    float  creg[2];
    {
        const float2* __restrict__ wxbp = g_wxb + nb * 32;
#pragma unroll
        for (int q = 0; q < 2; ++q) {
            int jl = (ntK + q) * 2 + ((lane & 3) >> 1);
            wxi[q] = wxbp[4 * jl + 0];
            wxf[q] = wxbp[4 * jl + 1];
            wxc[q] = wxbp[4 * jl + 2];
            wxo[q] = wxbp[4 * jl + 3];
            creg[q] = g_c[my_row * HDIM + nb * 8 + jl];
        }
    }

    // sync: warp 0 polls all 96 counters (lane l polls l, l+32, l+64), then
    // publishes step to SMEM flag; other warps spin on the flag.
    unsigned* __restrict__ relp = &g_ctr[(nb >> 3) * 8 + rw][0];
    const int c0i = lane, c1i = lane + 32, c2i = lane + 64;
    const unsigned* __restrict__ poll0 = &g_ctr[c0i % 12 * 8 + c0i / 12][0];
    const unsigned* __restrict__ poll1 = &g_ctr[c1i % 12 * 8 + c1i / 12][0];
    const unsigned* __restrict__ poll2 = &g_ctr[c2i % 12 * 8 + c2i / 12][0];

    for (int t = 0; t < SEQ; ++t) {
        const int par = t & 1;
        const __half* __restrict__ hin = g_h[par];
        __half* __restrict__ hout = g_h[par ^ 1];

        // ---- dataflow wait ----
        if (t > 0) {
            const unsigned tgt = 16u * (unsigned)t;
            if (wid == 0) {
                for (;;) {
                    unsigned v0, v1, v2;
                    asm volatile("ld.acquire.gpu.global.u32 %0, [%1];" : "=r"(v0) : "l"(poll0) : "memory");
                    asm volatile("ld.acquire.gpu.global.u32 %0, [%1];" : "=r"(v1) : "l"(poll1) : "memory");
                    asm volatile("ld.acquire.gpu.global.u32 %0, [%1];" : "=r"(v2) : "l"(poll2) : "memory");
                    bool ok = (v0 >= tgt) && (v1 >= tgt) && (v2 >= tgt);
                    if (__all_sync(0xffffffffu, ok)) break;
                }
                if (lane == 0) {
                    asm volatile("st.release.cta.shared.u32 [%0], %1;"
                                 :: "r"(flag_addr), "r"((unsigned)t) : "memory");
                }
                __syncwarp();
            } else {
                unsigned v;
                do {
                    asm volatile("ld.acquire.cta.shared.u32 %0, [%1];"
                                 : "=r"(v) : "r"(flag_addr) : "memory");
                } while (v < (unsigned)t);
            }
        }
        __syncwarp();

        float d[4][4];
#pragma unroll
        for (int i = 0; i < 4; i++)
#pragma unroll
            for (int k = 0; k < 4; k++) d[i][k] = 0.f;

        // per-warp A staging: 16 rows x 64 k fp16, XOR swizzle, buffer l%3
        auto issue = [&](int l) {
            const int g = hf * 6 + l;
            const uint32_t bufs = abase + (uint32_t)(l % 3) * 2048;
#pragma unroll
            for (int i = 0; i < 4; ++i) {
                int o = lane * 4 + i;            // 0..127
                int row = o >> 3, seg = o & 7;
                uint32_t dst = bufs + (uint32_t)(row * 128 + ((seg ^ (row & 7)) << 4));
                cpa16(dst, hin + (rw * 16 + row) * HDIM + g * 64 + seg * 8);
            }
            cp_commit();
        };

        issue(0); issue(1); issue(2);

#pragma unroll
        for (int l = 0; l < 6; ++l) {
            if (l < 4)       cp_wait2();
            else if (l == 4) cp_wait1();
            else             cp_wait0();
            __syncwarp();
            const int g = hf * 6 + l;
            const uint32_t abuf = abase + (uint32_t)(l % 3) * 2048;
            const uint32_t wch = sb + WS_BASE + (uint32_t)g * 4096;
#pragma unroll
            for (int ks = 0; ks < 4; ++ks) {
                const uint32_t asw = (uint32_t)((((ks << 1) | hsA) ^ li) << 4);
                const uint32_t bsw = (uint32_t)((((ks << 1) | hsB) ^ li) << 4);
                uint32_t a[4];
                ldsm4(a, abuf + aoffrow + asw);
#pragma unroll
                for (int p = 0; p < 2; ++p) {
                    uint32_t b[4];
                    ldsm4(b, wch + boffrow + (uint32_t)(p * 2048) + bsw);
                    mma_f16(d[2 * p],     a, b[0], b[1]);
                    mma_f16(d[2 * p + 1], a, b[2], b[3]);
                }
            }
            __syncwarp();
            if (l + 3 < 6) issue(l + 3);
        }

        // ---------------- split-K partial exchange (warp pair rw, rw+8) -------
        {
            float* ex = (float*)(smem + A_BASE + wid * 6144 + lane * 32);
#pragma unroll
            for (int k = 0; k < 4; ++k) { ex[k] = d[ntS][k]; ex[4 + k] = d[ntS + 1][k]; }
            asm volatile("bar.sync %0, 64;" :: "r"(1 + rw) : "memory");
            const float* px = (const float*)(smem + A_BASE + (wid ^ 8) * 6144 + lane * 32);
#pragma unroll
            for (int k = 0; k < 4; ++k) { d[ntK][k] += px[k]; d[ntK + 1][k] += px[4 + k]; }
            asm volatile("bar.sync %0, 64;" :: "r"(1 + rw) : "memory");
        }

        // ---------------- fused LSTM epilogue (kept n-tiles) ------------------
        const float xv = xrow[2 * t];
#pragma unroll
        for (int q = 0; q < 2; ++q) {
            const int nt = ntK + q;
            const int jl = nt * 2 + ((lane & 3) >> 1);
            float p0 = __shfl_xor_sync(0xffffffffu, d[nt][0], 1);
            float p1 = __shfl_xor_sync(0xffffffffu, d[nt][1], 1);
            float p2 = __shfl_xor_sync(0xffffffffu, d[nt][2], 1);
            float p3 = __shfl_xor_sync(0xffffffffu, d[nt][3], 1);
            float gi, gf, gc, go;
            if (!(lane & 1)) { gi = d[nt][0]; gf = d[nt][1]; gc = p0; go = p1; }
            else             { gi = p2;       gf = p3;       gc = d[nt][2]; go = d[nt][3]; }
            float pi = gi + xv * wxi[q].x + wxi[q].y;
            float pf = gf + xv * wxf[q].x + wxf[q].y;
            float pc = gc + xv * wxc[q].x + wxc[q].y;
            float po = go + xv * wxo[q].x + wxo[q].y;
            float ig = __fdividef(1.f, 1.f + __expf(-pi));
            float fg = __fdividef(1.f, 1.f + __expf(-pf));
            float thc = 1.f - __fdividef(2.f, 1.f + __expf(2.f * pc));
            float cn = fg * creg[q] + ig * thc;
            float thn = 1.f - __fdividef(2.f, 1.f + __expf(2.f * cn));
            float hn = po * thn;            // no sigmoid on output gate
            creg[q] = cn;
            hout[my_row * HDIM + nb * 8 + jl] = __float2half(hn);
        }

        // publish (release orders prior stores)
        if (t + 1 < SEQ) {
            __syncwarp();
            if (lane == 0) {
                asm volatile("red.release.gpu.global.add.u32 [%0], %1;"
                             :: "l"(relp), "r"(1u) : "memory");
            }
        }
    }
}

// ---------------------------------------------------------------------------
__global__ void out_final(const float* __restrict__ Wout,
                          const float* __restrict__ bout,
                          float* __restrict__ out) {
    int gtid = blockIdx.x * 128 + threadIdx.x;
    int r = gtid >> 5, lane = gtid & 31;
    float s = 0.f;
    for (int k = lane; k < HDIM; k += 32)
        s += __half2float(g_h[0][r * HDIM + k]) * Wout[k];
#pragma unroll
    for (int o = 16; o; o >>= 1) s += __shfl_xor_sync(0xffffffffu, s, o);
    if (lane == 0) out[r] = s + bout[0];
}

// ---------------------------------------------------------------------------
extern "C" void kernel_launch(void* const* d_in, const int* in_sizes, int n_in,
                              void* d_out, int out_size) {
    (void)in_sizes; (void)n_in; (void)out_size;
    const float* x    = (const float*)d_in[0];
    const float* h0   = (const float*)d_in[1];
    const float* c0   = (const float*)d_in[2];
    const float* Wi   = (const float*)d_in[3];
    const float* bi   = (const float*)d_in[4];
    const float* Wf   = (const float*)d_in[5];
    const float* bf   = (const float*)d_in[6];
    const float* Wc   = (const float*)d_in[7];
    const float* bc   = (const float*)d_in[8];
    const float* Wo   = (const float*)d_in[9];
    const float* bo   = (const float*)d_in[10];
    const float* Wout = (const float*)d_in[11];
    const float* bout = (const float*)d_in[12];
    float* out = (float*)d_out;

    static int configured = 0;
    if (!configured) {
        cudaFuncSetAttribute(lstm_persistent,
                             cudaFuncAttributeMaxDynamicSharedMemorySize, SMEM_TOTAL);
        configured = 1;
    }

    init_state<<<(ROWS * HDIM + 255) / 256, 256>>>(h0, c0);
    repack<<<(NCTA * NCHUNK * 2048 + 255) / 256, 256>>>(Wi, Wf, Wc, Wo, bi, bf, bc, bo);
    lstm_persistent<<<NCTA, 512, SMEM_TOTAL>>>(x);
    out_final<<<32, 128>>>(Wout, bout, out);
}